// round 15
// baseline (speedup 1.0000x reference)
#include <cuda_runtime.h>
#include <cuda_fp16.h>
#include <cstdint>
#include <math.h>

// Problem constants
constexpr int B_ROWS = 8192;   // batch
constexpr int FDIM   = 4096;   // features
constexpr int NINT   = 511;    // internal nodes
constexpr int NPAD   = 512;    // padded internal dim
constexpr int NLEAF  = 512;
constexpr int KOUT   = 1000;
constexpr int NPAD2  = 1024;   // padded output-class dim

// Scratch (device globals; allocation is forbidden)
__device__ __half g_wh[(size_t)NPAD * FDIM];         // W in fp16, row 511 zero
__device__ __half g_ps[(size_t)B_ROWS * NPAD];       // sigmoid(logits), fp16 (col 511 = 0.5, unused)
__device__ __half g_lp[(size_t)B_ROWS * NLEAF];      // leaf probabilities, fp16
__device__ __half g_distsT[(size_t)NPAD2 * NLEAF];   // softmax^T, rows [1000,1024) zero

// ---------------------------------------------------------------------------
// helpers
// ---------------------------------------------------------------------------
__device__ __forceinline__ uint32_t s2u(const void* p) {
    return (uint32_t)__cvta_generic_to_shared(p);
}

__device__ __forceinline__ void ldsm4(uint32_t* r, uint32_t addr) {
    asm volatile("ldmatrix.sync.aligned.m8n8.x4.shared.b16 {%0,%1,%2,%3}, [%4];"
        : "=r"(r[0]), "=r"(r[1]), "=r"(r[2]), "=r"(r[3]) : "r"(addr));
}

__device__ __forceinline__ void mma16(float* c, const uint32_t* a, uint32_t b0, uint32_t b1) {
    asm volatile(
        "mma.sync.aligned.m16n8k16.row.col.f32.f16.f16.f32 "
        "{%0,%1,%2,%3}, {%4,%5,%6,%7}, {%8,%9}, {%0,%1,%2,%3};\n"
        : "+f"(c[0]), "+f"(c[1]), "+f"(c[2]), "+f"(c[3])
        : "r"(a[0]), "r"(a[1]), "r"(a[2]), "r"(a[3]), "r"(b0), "r"(b1));
}

__device__ __forceinline__ void cpasync16(uint32_t dst, const void* src) {
    asm volatile("cp.async.cg.shared.global [%0], [%1], 16;" :: "r"(dst), "l"(src));
}

// mbarrier primitives
__device__ __forceinline__ void mbar_init(uint32_t a, uint32_t cnt) {
    asm volatile("mbarrier.init.shared.b64 [%0], %1;" :: "r"(a), "r"(cnt) : "memory");
}
__device__ __forceinline__ void mbar_arrive(uint32_t a) {
    asm volatile("mbarrier.arrive.shared.b64 _, [%0];" :: "r"(a) : "memory");
}
__device__ __forceinline__ void cp_arrive(uint32_t a) {
    asm volatile("cp.async.mbarrier.arrive.noinc.shared.b64 [%0];" :: "r"(a) : "memory");
}
__device__ __forceinline__ void mbar_wait(uint32_t a, uint32_t parity) {
    asm volatile(
        "{\n\t"
        ".reg .pred P;\n\t"
        "WAIT_%=:\n\t"
        "mbarrier.try_wait.parity.acquire.cta.shared::cta.b64 P, [%0], %1, 0x989680;\n\t"
        "@P bra.uni DONE_%=;\n\t"
        "bra.uni WAIT_%=;\n\t"
        "DONE_%=:\n\t"
        "}"
        :: "r"(a), "r"(parity) : "memory");
}

// 64B rows (32 halves), chunk 0..3 of 16B — XOR swizzle (validated R5/R8)
__device__ __forceinline__ uint32_t sw64(int row, int chunk) {
    return row * 64 + ((chunk ^ ((row >> 1) & 3)) << 4);
}

// pack 8 fp32 -> 8 fp16 in a uint4
__device__ __forceinline__ uint4 pack8(float4 a, float4 b) {
    uint4 r;
    __half2 h;
    h = __floats2half2_rn(a.x, a.y); r.x = *(uint32_t*)&h;
    h = __floats2half2_rn(a.z, a.w); r.y = *(uint32_t*)&h;
    h = __floats2half2_rn(b.x, b.y); r.z = *(uint32_t*)&h;
    h = __floats2half2_rn(b.z, b.w); r.w = *(uint32_t*)&h;
    return r;
}

// ---------------------------------------------------------------------------
// Merged prep kernel: conv_w | softmax  (branch on blockIdx.x) — conv_x is
// fused into gemm1 now, eliminating its 134MB DRAM round-trip.
// ---------------------------------------------------------------------------
constexpr int PREP_CONVW  = (NPAD * FDIM) / (256 * 8);     // 1024
constexpr int PREP_BLOCKS = PREP_CONVW + NLEAF;

__global__ void prep_kernel(const float* __restrict__ W,
                            const float* __restrict__ lp)
{
    const int bx = blockIdx.x;
    const int tid = threadIdx.x;

    if (bx < PREP_CONVW) {
        const size_t i = ((size_t)bx * 256 + tid) * 8;
        if (i < (size_t)NINT * FDIM) {
            const float4* s = (const float4*)(W + i);
            *(uint4*)(g_wh + i) = pack8(s[0], s[1]);
        } else {
            *(uint4*)(g_wh + i) = make_uint4(0, 0, 0, 0);
        }
        return;
    }

    // softmax for leaf row
    const int row = bx - PREP_CONVW;
    const float* src = lp + (size_t)row * KOUT;
    __shared__ float red[8];
    __shared__ float se[KOUT];

    float m = -1e30f;
    for (int i = tid; i < KOUT; i += 256) { float v = src[i]; se[i] = v; m = fmaxf(m, v); }
    #pragma unroll
    for (int o = 16; o > 0; o >>= 1) m = fmaxf(m, __shfl_xor_sync(0xffffffffu, m, o));
    if ((tid & 31) == 0) red[tid >> 5] = m;
    __syncthreads();
    if (tid < 32) {
        float v = (tid < 8) ? red[tid] : -1e30f;
        #pragma unroll
        for (int o = 4; o > 0; o >>= 1) v = fmaxf(v, __shfl_xor_sync(0xffffffffu, v, o));
        if (tid == 0) red[0] = v;
    }
    __syncthreads();
    m = red[0];
    __syncthreads();

    float s = 0.f;
    for (int i = tid; i < KOUT; i += 256) { float e = __expf(se[i] - m); se[i] = e; s += e; }
    #pragma unroll
    for (int o = 16; o > 0; o >>= 1) s += __shfl_xor_sync(0xffffffffu, s, o);
    if ((tid & 31) == 0) red[tid >> 5] = s;
    __syncthreads();
    if (tid < 32) {
        float v = (tid < 8) ? red[tid] : 0.f;
        #pragma unroll
        for (int o = 4; o > 0; o >>= 1) v += __shfl_xor_sync(0xffffffffu, v, o);
        if (tid == 0) red[0] = v;
    }
    __syncthreads();
    const float inv = 1.f / red[0];
    for (int i = tid; i < KOUT; i += 256)
        g_distsT[(size_t)i * NLEAF + row] = __float2half_rn(se[i] * inv);
    for (int i = KOUT + tid; i < NPAD2; i += 256)
        g_distsT[(size_t)i * NLEAF + row] = __float2half_rn(0.f);
}

// ---------------------------------------------------------------------------
// GEMM1 (fused xs-convert): ps = sigmoid(xs_fp32 @ wh^T + b)
// CTA 128x128, 8 warps (32x64), BK=32, mbarrier ring 6 stages x 16KB, D=4.
// A path: LDG.128 fp32 (prefetched at loop top) -> pack8 -> swizzled STS ->
//         mbar_arrive.  B path: cp.async fp16 -> cp_arrive.
// full[s] init 512 (256 STS arrivals + 256 cp completions); empty[s] 256.
// Two-phase compute (R13) to keep regs <= 128 with the 16-float prefetch.
// ---------------------------------------------------------------------------
constexpr int STAGE_SMEM = 6 * 16384 + 128;   // 96KB stages + mbarriers

__global__ __launch_bounds__(256, 2)
void gemm1_kernel(const float* __restrict__ xs, const float* __restrict__ bias)
{
    extern __shared__ __align__(16) char smem[];
    const uint32_t sb = s2u(smem);
    const uint32_t MBF = sb + 98304u;         // full[6]
    const uint32_t MBE = sb + 98304u + 48u;   // empty[6]
    const int tid = threadIdx.x, warp = tid >> 5, lane = tid & 31;
    const int wm = warp & 3, wn = warp >> 2;
    const int tn = blockIdx.x, tm = blockIdx.y;
    if (tid == 0) {
        #pragma unroll
        for (int s = 0; s < 6; s++) { mbar_init(MBF + s * 8, 512); mbar_init(MBE + s * 8, 256); }
    }
    __syncthreads();

    float c[2][8][4];
    #pragma unroll
    for (int i = 0; i < 2; i++)
        #pragma unroll
        for (int j = 0; j < 8; j++)
            #pragma unroll
            for (int k = 0; k < 4; k++) c[i][j][k] = 0.f;

    // hoisted ks=0 fragment offsets; ks=1 = XOR 0x20 (swizzle algebra, R14)
    uint32_t a_off[2], b_off[4];
    {
        const int kc = lane >> 4;
        #pragma unroll
        for (int mt = 0; mt < 2; mt++)
            a_off[mt] = sw64(wm * 32 + mt * 16 + (lane & 15), kc);
        #pragma unroll
        for (int nt = 0; nt < 4; nt++)
            b_off[nt] = 8192u + sw64(wn * 64 + nt * 16 + (lane & 15), kc);
    }
    const int lrow = tid >> 1, lch = (tid & 1) * 2;
    const uint32_t st_a0 = sw64(lrow, lch), st_a1 = sw64(lrow, lch + 1);
    const float*  Ag = xs   + (size_t)(tm * 128 + lrow) * FDIM + (tid & 1) * 16;
    const __half* Bg = g_wh + (size_t)(tn * 128 + lrow) * FDIM + (tid & 1) * 16;

    float4 ra[4];
    auto ldgA = [&](int kn) {
        const float4* ap = (const float4*)(Ag + kn * 32);
        ra[0] = ap[0]; ra[1] = ap[1]; ra[2] = ap[2]; ra[3] = ap[3];
    };
    auto produce = [&](int kn, int buf) {
        const uint32_t St = sb + buf * 16384;
        const __half* bg = Bg + kn * 32;
        cpasync16(St + 8192 + st_a0, bg);
        cpasync16(St + 8192 + st_a1, bg + 8);
        cp_arrive(MBF + buf * 8);
        *(uint4*)(smem + (St - sb) + st_a0) = pack8(ra[0], ra[1]);
        *(uint4*)(smem + (St - sb) + st_a1) = pack8(ra[2], ra[3]);
        mbar_arrive(MBF + buf * 8);
    };
    auto compute = [&](int buf) {
        const uint32_t St = sb + buf * 16384;
        #pragma unroll
        for (int ks = 0; ks < 2; ks++) {
            const uint32_t x = ks ? 0x20u : 0u;
            uint32_t a[2][4], b[4][4];
            #pragma unroll
            for (int mt = 0; mt < 2; mt++) ldsm4(a[mt], St + (a_off[mt] ^ x));
            #pragma unroll
            for (int nt = 0; nt < 4; nt++) ldsm4(b[nt], St + (b_off[nt] ^ x));
            #pragma unroll
            for (int mt = 0; mt < 2; mt++)
                #pragma unroll
                for (int nt = 0; nt < 4; nt++) {
                    mma16(c[mt][nt * 2],     a[mt], b[nt][0], b[nt][2]);
                    mma16(c[mt][nt * 2 + 1], a[mt], b[nt][1], b[nt][3]);
                }
        }
    };

    constexpr int KT = FDIM / 32;   // 128
    // prologue: fill stages 0..3
    #pragma unroll
    for (int p = 0; p < 4; p++) { ldgA(p); produce(p, p); }

    int sc = 0, fpar = 0, rs = 3, rpar = 1;
    for (int kt = 0; kt < KT; kt++) {
        const int kn = kt + 4;
        if (kn < KT) ldgA(kn);                 // prefetch fp32 A (regs)
        mbar_wait(MBF + sc * 8, fpar);
        compute(sc);
        mbar_arrive(MBE + sc * 8);
        rs++; if (rs == 6) { rs = 0; rpar ^= 1; }
        if (kn < KT) {
            if (kt >= 2) mbar_wait(MBE + rs * 8, rpar);
            produce(kn, rs);
        }
        sc++; if (sc == 6) { sc = 0; fpar ^= 1; }
    }

    // Epilogue: bias + sigmoid -> g_ps (fp16)
    const int g = lane >> 2, tg = lane & 3;
    #pragma unroll
    for (int mt = 0; mt < 2; mt++) {
        #pragma unroll
        for (int j = 0; j < 8; j++) {
            const int col = tn * 128 + wn * 64 + j * 8 + 2 * tg;
            const float bb0 = (col     < NINT) ? __ldg(bias + col)     : 0.f;
            const float bb1 = (col + 1 < NINT) ? __ldg(bias + col + 1) : 0.f;
            const int row0 = tm * 128 + wm * 32 + mt * 16 + g;
            float v0 = c[mt][j][0] + bb0;
            float v1 = c[mt][j][1] + bb1;
            float v2 = c[mt][j][2] + bb0;
            float v3 = c[mt][j][3] + bb1;
            __half2 p0 = __floats2half2_rn(1.f / (1.f + __expf(-v0)), 1.f / (1.f + __expf(-v1)));
            __half2 p1 = __floats2half2_rn(1.f / (1.f + __expf(-v2)), 1.f / (1.f + __expf(-v3)));
            *(__half2*)&g_ps[(size_t)row0       * NPAD + col] = p0;
            *(__half2*)&g_ps[(size_t)(row0 + 8) * NPAD + col] = p1;
        }
    }
}

// ---------------------------------------------------------------------------
// GEMM2: out = leaf_prob[8192,512] @ distsT^T[512, 1024pad]   grid (8, 64)
// R14 core: mbarrier ring, batched 12-LDSM schedule, XOR-0x20 ks derivation.
// ---------------------------------------------------------------------------
__global__ __launch_bounds__(256, 2)
void gemm2_kernel(float* __restrict__ out)
{
    extern __shared__ __align__(16) char smem[];
    const uint32_t sb = s2u(smem);
    const uint32_t MBF = sb + 98304u;
    const uint32_t MBE = sb + 98304u + 48u;
    const int tid = threadIdx.x, warp = tid >> 5, lane = tid & 31;
    const int wm = warp & 3, wn = warp >> 2;
    const int tn = blockIdx.x, tm = blockIdx.y;
    if (tid == 0) {
        #pragma unroll
        for (int s = 0; s < 6; s++) { mbar_init(MBF + s * 8, 256); mbar_init(MBE + s * 8, 256); }
    }
    __syncthreads();

    float c[2][8][4];
    #pragma unroll
    for (int i = 0; i < 2; i++)
        #pragma unroll
        for (int j = 0; j < 8; j++)
            #pragma unroll
            for (int k = 0; k < 4; k++) c[i][j][k] = 0.f;

    uint32_t a_off[2], b_off[4];
    {
        const int kc = lane >> 4;
        #pragma unroll
        for (int mt = 0; mt < 2; mt++)
            a_off[mt] = sw64(wm * 32 + mt * 16 + (lane & 15), kc);
        #pragma unroll
        for (int nt = 0; nt < 4; nt++)
            b_off[nt] = 8192u + sw64(wn * 64 + nt * 16 + (lane & 15), kc);
    }
    const int lrow = tid >> 1, lch = (tid & 1) * 2;
    const uint32_t st_a0 = sw64(lrow, lch), st_a1 = sw64(lrow, lch + 1);
    const __half* Ag = g_lp     + (size_t)(tm * 128 + lrow) * NLEAF + (tid & 1) * 16;
    const __half* Bg = g_distsT + (size_t)(tn * 128 + lrow) * NLEAF + (tid & 1) * 16;

    auto issue = [&](int kn, int buf) {
        const uint32_t St = sb + buf * 16384;
        const __half* ag = Ag + kn * 32;
        const __half* bg = Bg + kn * 32;
        cpasync16(St + st_a0,        ag);
        cpasync16(St + st_a1,        ag + 8);
        cpasync16(St + 8192 + st_a0, bg);
        cpasync16(St + 8192 + st_a1, bg + 8);
        cp_arrive(MBF + buf * 8);
    };
    auto compute = [&](int buf) {
        const uint32_t St = sb + buf * 16384;
        uint32_t a[2][2][4], b[2][4][4];
        #pragma unroll
        for (int mt = 0; mt < 2; mt++) {
            ldsm4(a[0][mt], St + a_off[mt]);
            ldsm4(a[1][mt], St + (a_off[mt] ^ 0x20u));
        }
        #pragma unroll
        for (int nt = 0; nt < 4; nt++) {
            ldsm4(b[0][nt], St + b_off[nt]);
            ldsm4(b[1][nt], St + (b_off[nt] ^ 0x20u));
        }
        #pragma unroll
        for (int ks = 0; ks < 2; ks++)
            #pragma unroll
            for (int mt = 0; mt < 2; mt++)
                #pragma unroll
                for (int nt = 0; nt < 4; nt++) {
                    mma16(c[mt][nt * 2],     a[ks][mt], b[ks][nt][0], b[ks][nt][2]);
                    mma16(c[mt][nt * 2 + 1], a[ks][mt], b[ks][nt][1], b[ks][nt][3]);
                }
    };

    constexpr int KT = NLEAF / 32;  // 16
    issue(0, 0); issue(1, 1); issue(2, 2); issue(3, 3);
    int sc = 0, fpar = 0, rs = 3, rpar = 1;
    for (int kt = 0; kt < KT; kt++) {
        mbar_wait(MBF + sc * 8, fpar);
        compute(sc);
        mbar_arrive(MBE + sc * 8);
        rs++; if (rs == 6) { rs = 0; rpar ^= 1; }
        const int kn = kt + 4;
        if (kn < KT) {
            if (kt >= 2) mbar_wait(MBE + rs * 8, rpar);
            issue(kn, rs);
        }
        sc++; if (sc == 6) { sc = 0; fpar ^= 1; }
    }

    const int g = lane >> 2, tg = lane & 3;
    #pragma unroll
    for (int mt = 0; mt < 2; mt++) {
        #pragma unroll
        for (int j = 0; j < 8; j++) {
            const int col = tn * 128 + wn * 64 + j * 8 + 2 * tg;
            if (col < KOUT) {   // col even, KOUT even -> pair in-bounds
                const int row0 = tm * 128 + wm * 32 + mt * 16 + g;
                *(float2*)&out[(size_t)row0       * KOUT + col] =
                    make_float2(c[mt][j][0], c[mt][j][1]);
                *(float2*)&out[(size_t)(row0 + 8) * KOUT + col] =
                    make_float2(c[mt][j][2], c[mt][j][3]);
            }
        }
    }
}

// ---------------------------------------------------------------------------
// Leaf probabilities: one block per row, 256 threads x 2 leaves, fp16 in/out
// ---------------------------------------------------------------------------
__global__ __launch_bounds__(256)
void leaf_kernel()
{
    __shared__ float sp[NPAD];
    const int row = blockIdx.x;
    const int tid = threadIdx.x;
    {
        const __half2 h = *(const __half2*)&g_ps[(size_t)row * NPAD + 2 * tid];
        const float2 f = __half22float2(h);
        sp[2 * tid]     = f.x;
        sp[2 * tid + 1] = f.y;
    }
    __syncthreads();
    #pragma unroll
    for (int r = 0; r < 2; r++) {
        const int j = tid + r * 256;
        float prod = 1.f;
        int node = 0;
        #pragma unroll
        for (int t = 0; t < 9; t++) {
            const int bit = (j >> (8 - t)) & 1;
            const float p = sp[node];
            prod *= bit ? p : (1.f - p);
            node = 2 * node + 1 + bit;
        }
        g_lp[(size_t)row * NLEAF + j] = __float2half_rn(prod);
    }
}

// ---------------------------------------------------------------------------
// Launch
// ---------------------------------------------------------------------------
extern "C" void kernel_launch(void* const* d_in, const int* in_sizes, int n_in,
                              void* d_out, int out_size)
{
    const float* xs          = (const float*)d_in[0];   // [8192, 4096]
    const float* W           = (const float*)d_in[1];   // [511, 4096]
    const float* b           = (const float*)d_in[2];   // [511]
    const float* leaf_params = (const float*)d_in[3];   // [512, 1000]
    float* out = (float*)d_out;                         // [8192, 1000]

    cudaFuncSetAttribute(gemm1_kernel, cudaFuncAttributeMaxDynamicSharedMemorySize, STAGE_SMEM);
    cudaFuncSetAttribute(gemm2_kernel, cudaFuncAttributeMaxDynamicSharedMemorySize, STAGE_SMEM);

    prep_kernel<<<PREP_BLOCKS, 256>>>(W, leaf_params);
    gemm1_kernel<<<dim3(4, 64), 256, STAGE_SMEM>>>(xs, b);
    leaf_kernel<<<B_ROWS, 256>>>();
    gemm2_kernel<<<dim3(8, 64), 256, STAGE_SMEM>>>(out);
}

// round 16
// speedup vs baseline: 1.0665x; 1.0665x over previous
#include <cuda_runtime.h>
#include <cuda_fp16.h>
#include <cstdint>
#include <math.h>

// Problem constants
constexpr int B_ROWS = 8192;   // batch
constexpr int FDIM   = 4096;   // features
constexpr int NINT   = 511;    // internal nodes
constexpr int NPAD   = 512;    // padded internal dim
constexpr int NLEAF  = 512;
constexpr int KOUT   = 1000;
constexpr int NPAD2  = 1024;   // padded output-class dim

// Scratch (device globals; allocation is forbidden)
__device__ __half g_xh[(size_t)B_ROWS * FDIM];       // xs in fp16
__device__ __half g_wh[(size_t)NPAD * FDIM];         // W in fp16, row 511 zero
__device__ __half g_ps[(size_t)B_ROWS * NPAD];       // sigmoid(logits), fp16 (col 511 = 0.5, unused)
__device__ __half g_lp[(size_t)B_ROWS * NLEAF];      // leaf probabilities, fp16
__device__ __half g_distsT[(size_t)NPAD2 * NLEAF];   // softmax^T, rows [1000,1024) zero

// ---------------------------------------------------------------------------
// helpers
// ---------------------------------------------------------------------------
__device__ __forceinline__ uint32_t s2u(const void* p) {
    return (uint32_t)__cvta_generic_to_shared(p);
}

__device__ __forceinline__ void ldsm4(uint32_t* r, uint32_t addr) {
    asm volatile("ldmatrix.sync.aligned.m8n8.x4.shared.b16 {%0,%1,%2,%3}, [%4];"
        : "=r"(r[0]), "=r"(r[1]), "=r"(r[2]), "=r"(r[3]) : "r"(addr));
}

__device__ __forceinline__ void mma16(float* c, const uint32_t* a, uint32_t b0, uint32_t b1) {
    asm volatile(
        "mma.sync.aligned.m16n8k16.row.col.f32.f16.f16.f32 "
        "{%0,%1,%2,%3}, {%4,%5,%6,%7}, {%8,%9}, {%0,%1,%2,%3};\n"
        : "+f"(c[0]), "+f"(c[1]), "+f"(c[2]), "+f"(c[3])
        : "r"(a[0]), "r"(a[1]), "r"(a[2]), "r"(a[3]), "r"(b0), "r"(b1));
}

__device__ __forceinline__ void cpasync16(uint32_t dst, const void* src) {
    asm volatile("cp.async.cg.shared.global [%0], [%1], 16;" :: "r"(dst), "l"(src));
}

// mbarrier primitives
__device__ __forceinline__ void mbar_init(uint32_t a, uint32_t cnt) {
    asm volatile("mbarrier.init.shared.b64 [%0], %1;" :: "r"(a), "r"(cnt) : "memory");
}
__device__ __forceinline__ void mbar_arrive(uint32_t a) {
    asm volatile("mbarrier.arrive.shared.b64 _, [%0];" :: "r"(a) : "memory");
}
__device__ __forceinline__ void cp_arrive(uint32_t a) {
    asm volatile("cp.async.mbarrier.arrive.noinc.shared.b64 [%0];" :: "r"(a) : "memory");
}
__device__ __forceinline__ void mbar_wait(uint32_t a, uint32_t parity) {
    asm volatile(
        "{\n\t"
        ".reg .pred P;\n\t"
        "WAIT_%=:\n\t"
        "mbarrier.try_wait.parity.acquire.cta.shared::cta.b64 P, [%0], %1, 0x989680;\n\t"
        "@P bra.uni DONE_%=;\n\t"
        "bra.uni WAIT_%=;\n\t"
        "DONE_%=:\n\t"
        "}"
        :: "r"(a), "r"(parity) : "memory");
}

// 64B rows (32 halves), chunk 0..3 of 16B — XOR swizzle (validated R5/R8)
__device__ __forceinline__ uint32_t sw64(int row, int chunk) {
    return row * 64 + ((chunk ^ ((row >> 1) & 3)) << 4);
}

// pack 8 fp32 -> 8 fp16 in a uint4
__device__ __forceinline__ uint4 pack8(float4 a, float4 b) {
    uint4 r;
    __half2 h;
    h = __floats2half2_rn(a.x, a.y); r.x = *(uint32_t*)&h;
    h = __floats2half2_rn(a.z, a.w); r.y = *(uint32_t*)&h;
    h = __floats2half2_rn(b.x, b.y); r.z = *(uint32_t*)&h;
    h = __floats2half2_rn(b.z, b.w); r.w = *(uint32_t*)&h;
    return r;
}

// ---------------------------------------------------------------------------
// Merged prep kernel: conv_x | conv_w | softmax  (branch on blockIdx.x)
// ---------------------------------------------------------------------------
constexpr int PREP_CONVX  = (B_ROWS * FDIM) / (256 * 8);   // 16384
constexpr int PREP_CONVW  = (NPAD * FDIM) / (256 * 8);     // 1024
constexpr int PREP_BLOCKS = PREP_CONVX + PREP_CONVW + NLEAF;

__global__ void prep_kernel(const float* __restrict__ xs,
                            const float* __restrict__ W,
                            const float* __restrict__ lp)
{
    const int bx = blockIdx.x;
    const int tid = threadIdx.x;

    if (bx < PREP_CONVX) {
        const size_t i = ((size_t)bx * 256 + tid) * 8;
        const float4* s = (const float4*)(xs + i);
        *(uint4*)(g_xh + i) = pack8(s[0], s[1]);
        return;
    }
    if (bx < PREP_CONVX + PREP_CONVW) {
        const size_t i = ((size_t)(bx - PREP_CONVX) * 256 + tid) * 8;
        if (i < (size_t)NINT * FDIM) {
            const float4* s = (const float4*)(W + i);
            *(uint4*)(g_wh + i) = pack8(s[0], s[1]);
        } else {
            *(uint4*)(g_wh + i) = make_uint4(0, 0, 0, 0);
        }
        return;
    }

    // softmax for leaf row
    const int row = bx - PREP_CONVX - PREP_CONVW;
    const float* src = lp + (size_t)row * KOUT;
    __shared__ float red[8];
    __shared__ float se[KOUT];

    float m = -1e30f;
    for (int i = tid; i < KOUT; i += 256) { float v = src[i]; se[i] = v; m = fmaxf(m, v); }
    #pragma unroll
    for (int o = 16; o > 0; o >>= 1) m = fmaxf(m, __shfl_xor_sync(0xffffffffu, m, o));
    if ((tid & 31) == 0) red[tid >> 5] = m;
    __syncthreads();
    if (tid < 32) {
        float v = (tid < 8) ? red[tid] : -1e30f;
        #pragma unroll
        for (int o = 4; o > 0; o >>= 1) v = fmaxf(v, __shfl_xor_sync(0xffffffffu, v, o));
        if (tid == 0) red[0] = v;
    }
    __syncthreads();
    m = red[0];
    __syncthreads();

    float s = 0.f;
    for (int i = tid; i < KOUT; i += 256) { float e = __expf(se[i] - m); se[i] = e; s += e; }
    #pragma unroll
    for (int o = 16; o > 0; o >>= 1) s += __shfl_xor_sync(0xffffffffu, s, o);
    if ((tid & 31) == 0) red[tid >> 5] = s;
    __syncthreads();
    if (tid < 32) {
        float v = (tid < 8) ? red[tid] : 0.f;
        #pragma unroll
        for (int o = 4; o > 0; o >>= 1) v += __shfl_xor_sync(0xffffffffu, v, o);
        if (tid == 0) red[0] = v;
    }
    __syncthreads();
    const float inv = 1.f / red[0];
    for (int i = tid; i < KOUT; i += 256)
        g_distsT[(size_t)i * NLEAF + row] = __float2half_rn(se[i] * inv);
    for (int i = KOUT + tid; i < NPAD2; i += 256)
        g_distsT[(size_t)i * NLEAF + row] = __float2half_rn(0.f);
}

// ---------------------------------------------------------------------------
// Shared GEMM core (R14 base): CTA 128x128, 8 warps (32x64), BK=32,
// mbarrier ring 6 stages x 16KB, issue-ahead D=4, batched 12-LDSM schedule.
// NEW: statically scheduled ring — peel kt=0..5 (literal stages/parities),
// then 6-wide unrolled bodies (all stage indices & smem bases compile-time
// constants; only parity bits fp/rp are runtime, flipped once per period),
// then a dynamic tail. Schedule verified element-by-element vs the proven
// R13/R14 dynamic trace.
// ---------------------------------------------------------------------------
#define GEMM_CORE(Aptr, Astride, Bptr, Bstride, KT)                              \
    extern __shared__ __align__(16) char smem[];                                  \
    const uint32_t sb = s2u(smem);                                                \
    const uint32_t MBF = sb + 98304u;         /* full[6]  */                      \
    const uint32_t MBE = sb + 98304u + 48u;   /* empty[6] */                      \
    const int tid = threadIdx.x, warp = tid >> 5, lane = tid & 31;                \
    const int wm = warp & 3, wn = warp >> 2;                                      \
    const int tn = blockIdx.x, tm = blockIdx.y;                                   \
    if (tid == 0) {                                                               \
        _Pragma("unroll")                                                         \
        for (int s = 0; s < 6; s++) { mbar_init(MBF + s * 8, 256); mbar_init(MBE + s * 8, 256); } \
    }                                                                             \
    __syncthreads();                                                              \
    float c[2][8][4];                                                             \
    _Pragma("unroll")                                                             \
    for (int i = 0; i < 2; i++)                                                   \
        _Pragma("unroll")                                                         \
        for (int j = 0; j < 8; j++)                                               \
            _Pragma("unroll")                                                     \
            for (int k = 0; k < 4; k++) c[i][j][k] = 0.f;                         \
    uint32_t a_off[2], b_off[4];                                                  \
    {                                                                             \
        const int kc = lane >> 4;                                                 \
        _Pragma("unroll")                                                         \
        for (int mt = 0; mt < 2; mt++)                                            \
            a_off[mt] = sw64(wm * 32 + mt * 16 + (lane & 15), kc);                \
        _Pragma("unroll")                                                         \
        for (int nt = 0; nt < 4; nt++)                                            \
            b_off[nt] = 8192u + sw64(wn * 64 + nt * 16 + (lane & 15), kc);        \
    }                                                                             \
    const int lrow = tid >> 1, lch = (tid & 1) * 2;                               \
    const uint32_t st_a0 = sw64(lrow, lch), st_a1 = sw64(lrow, lch + 1);          \
    const __half* Ag = (Aptr) + (size_t)(tm * 128 + lrow) * (Astride) + (tid & 1) * 16; \
    const __half* Bg = (Bptr) + (size_t)(tn * 128 + lrow) * (Bstride) + (tid & 1) * 16; \
    auto issue = [&](int kn, int buf) {                                           \
        const uint32_t St = sb + buf * 16384;                                     \
        const __half* ag = Ag + kn * 32;                                          \
        const __half* bg = Bg + kn * 32;                                          \
        cpasync16(St + st_a0,        ag);                                         \
        cpasync16(St + st_a1,        ag + 8);                                     \
        cpasync16(St + 8192 + st_a0, bg);                                         \
        cpasync16(St + 8192 + st_a1, bg + 8);                                     \
        cp_arrive(MBF + buf * 8);                                                 \
    };                                                                            \
    auto compute = [&](int buf) {                                                 \
        const uint32_t St = sb + buf * 16384;                                     \
        uint32_t a[2][2][4], b[2][4][4];                                          \
        _Pragma("unroll")                                                         \
        for (int mt = 0; mt < 2; mt++) {                                          \
            ldsm4(a[0][mt], St + a_off[mt]);                                      \
            ldsm4(a[1][mt], St + (a_off[mt] ^ 0x20u));                            \
        }                                                                         \
        _Pragma("unroll")                                                         \
        for (int nt = 0; nt < 4; nt++) {                                          \
            ldsm4(b[0][nt], St + b_off[nt]);                                      \
            ldsm4(b[1][nt], St + (b_off[nt] ^ 0x20u));                            \
        }                                                                         \
        _Pragma("unroll")                                                         \
        for (int ks = 0; ks < 2; ks++)                                            \
            _Pragma("unroll")                                                     \
            for (int mt = 0; mt < 2; mt++)                                        \
                _Pragma("unroll")                                                 \
                for (int nt = 0; nt < 4; nt++) {                                  \
                    mma16(c[mt][nt * 2],     a[ks][mt], b[ks][nt][0], b[ks][nt][2]); \
                    mma16(c[mt][nt * 2 + 1], a[ks][mt], b[ks][nt][1], b[ks][nt][3]); \
                }                                                                 \
    };                                                                            \
    /* prologue: fill stages 0..3 */                                              \
    issue(0, 0); issue(1, 1); issue(2, 2); issue(3, 3);                           \
    /* peel kt=0..5 (literal stages, parity 0; empty-waits start at kt=2) */      \
    mbar_wait(MBF + 0,  0); compute(0); mbar_arrive(MBE + 0);                     \
                                          issue(4, 4);                            \
    mbar_wait(MBF + 8,  0); compute(1); mbar_arrive(MBE + 8);                     \
                                          issue(5, 5);                            \
    mbar_wait(MBF + 16, 0); compute(2); mbar_arrive(MBE + 16);                    \
        mbar_wait(MBE + 0,  0); issue(6, 0);                                      \
    mbar_wait(MBF + 24, 0); compute(3); mbar_arrive(MBE + 24);                    \
        mbar_wait(MBE + 8,  0); issue(7, 1);                                      \
    mbar_wait(MBF + 32, 0); compute(4); mbar_arrive(MBE + 32);                    \
        mbar_wait(MBE + 16, 0); issue(8, 2);                                      \
    mbar_wait(MBF + 40, 0); compute(5); mbar_arrive(MBE + 40);                    \
        mbar_wait(MBE + 24, 0); issue(9, 3);                                      \
    int fp = 1, rp = 0;                                                           \
    constexpr int TAILS = (((KT) - 10) / 6) * 6 + 6;                              \
    for (int kt0 = 6; kt0 < TAILS; kt0 += 6) {                                    \
        mbar_wait(MBF + 0,  fp); compute(0); mbar_arrive(MBE + 0);                \
            mbar_wait(MBE + 32, rp); issue(kt0 + 4, 4);                           \
        mbar_wait(MBF + 8,  fp); compute(1); mbar_arrive(MBE + 8);                \
            mbar_wait(MBE + 40, rp); issue(kt0 + 5, 5);                           \
        mbar_wait(MBF + 16, fp); compute(2); mbar_arrive(MBE + 16);               \
            rp ^= 1; mbar_wait(MBE + 0,  rp); issue(kt0 + 6, 0);                  \
        mbar_wait(MBF + 24, fp); compute(3); mbar_arrive(MBE + 24);               \
            mbar_wait(MBE + 8,  rp); issue(kt0 + 7, 1);                           \
        mbar_wait(MBF + 32, fp); compute(4); mbar_arrive(MBE + 32);               \
            mbar_wait(MBE + 16, rp); issue(kt0 + 8, 2);                           \
        mbar_wait(MBF + 40, fp); compute(5); mbar_arrive(MBE + 40);               \
            mbar_wait(MBE + 24, rp); issue(kt0 + 9, 3);                           \
        fp ^= 1;                                                                  \
    }                                                                             \
    /* tail: dynamic, continuing exact ring state (sc=0, rs=3, fp, rp) */         \
    {                                                                             \
        int sc = 0, rs = 3;                                                       \
        for (int kt = TAILS; kt < (KT); kt++) {                                   \
            mbar_wait(MBF + sc * 8, fp);                                          \
            compute(sc);                                                          \
            mbar_arrive(MBE + sc * 8);                                            \
            rs++; if (rs == 6) { rs = 0; rp ^= 1; }                               \
            const int kn = kt + 4;                                                \
            if (kn < (KT)) { mbar_wait(MBE + rs * 8, rp); issue(kn, rs); }        \
            sc++; if (sc == 6) { sc = 0; fp ^= 1; }                               \
        }                                                                         \
    }

constexpr int STAGE_SMEM = 6 * 16384 + 128;   // 96KB stages + mbarriers

// ---------------------------------------------------------------------------
// GEMM1: ps = sigmoid(xh @ wh^T + b)   grid (4, 64), 256 threads, fp16 out
// ---------------------------------------------------------------------------
__global__ __launch_bounds__(256, 2)
void gemm1_kernel(const float* __restrict__ bias)
{
    GEMM_CORE(g_xh, FDIM, g_wh, FDIM, FDIM / 32)

    const int g = lane >> 2, tg = lane & 3;
    #pragma unroll
    for (int mt = 0; mt < 2; mt++) {
        #pragma unroll
        for (int j = 0; j < 8; j++) {
            const int col = tn * 128 + wn * 64 + j * 8 + 2 * tg;
            const float bb0 = (col     < NINT) ? __ldg(bias + col)     : 0.f;
            const float bb1 = (col + 1 < NINT) ? __ldg(bias + col + 1) : 0.f;
            const int row0 = tm * 128 + wm * 32 + mt * 16 + g;
            float v0 = c[mt][j][0] + bb0;
            float v1 = c[mt][j][1] + bb1;
            float v2 = c[mt][j][2] + bb0;
            float v3 = c[mt][j][3] + bb1;
            __half2 p0 = __floats2half2_rn(1.f / (1.f + __expf(-v0)), 1.f / (1.f + __expf(-v1)));
            __half2 p1 = __floats2half2_rn(1.f / (1.f + __expf(-v2)), 1.f / (1.f + __expf(-v3)));
            *(__half2*)&g_ps[(size_t)row0       * NPAD + col] = p0;
            *(__half2*)&g_ps[(size_t)(row0 + 8) * NPAD + col] = p1;
        }
    }
}

// ---------------------------------------------------------------------------
// GEMM2: out = leaf_prob[8192,512] @ distsT^T[512, 1024pad]   grid (8, 64)
// ---------------------------------------------------------------------------
__global__ __launch_bounds__(256, 2)
void gemm2_kernel(float* __restrict__ out)
{
    GEMM_CORE(g_lp, NLEAF, g_distsT, NLEAF, NLEAF / 32)

    const int g = lane >> 2, tg = lane & 3;
    #pragma unroll
    for (int mt = 0; mt < 2; mt++) {
        #pragma unroll
        for (int j = 0; j < 8; j++) {
            const int col = tn * 128 + wn * 64 + j * 8 + 2 * tg;
            if (col < KOUT) {   // col even, KOUT even -> pair in-bounds
                const int row0 = tm * 128 + wm * 32 + mt * 16 + g;
                *(float2*)&out[(size_t)row0       * KOUT + col] =
                    make_float2(c[mt][j][0], c[mt][j][1]);
                *(float2*)&out[(size_t)(row0 + 8) * KOUT + col] =
                    make_float2(c[mt][j][2], c[mt][j][3]);
            }
        }
    }
}

// ---------------------------------------------------------------------------
// Leaf probabilities: one block per row, 256 threads x 2 leaves, fp16 in/out
// ---------------------------------------------------------------------------
__global__ __launch_bounds__(256)
void leaf_kernel()
{
    __shared__ float sp[NPAD];
    const int row = blockIdx.x;
    const int tid = threadIdx.x;
    {
        const __half2 h = *(const __half2*)&g_ps[(size_t)row * NPAD + 2 * tid];
        const float2 f = __half22float2(h);
        sp[2 * tid]     = f.x;
        sp[2 * tid + 1] = f.y;
    }
    __syncthreads();
    #pragma unroll
    for (int r = 0; r < 2; r++) {
        const int j = tid + r * 256;
        float prod = 1.f;
        int node = 0;
        #pragma unroll
        for (int t = 0; t < 9; t++) {
            const int bit = (j >> (8 - t)) & 1;
            const float p = sp[node];
            prod *= bit ? p : (1.f - p);
            node = 2 * node + 1 + bit;
        }
        g_lp[(size_t)row * NLEAF + j] = __float2half_rn(prod);
    }
}

// ---------------------------------------------------------------------------
// Launch
// ---------------------------------------------------------------------------
extern "C" void kernel_launch(void* const* d_in, const int* in_sizes, int n_in,
                              void* d_out, int out_size)
{
    const float* xs          = (const float*)d_in[0];   // [8192, 4096]
    const float* W           = (const float*)d_in[1];   // [511, 4096]
    const float* b           = (const float*)d_in[2];   // [511]
    const float* leaf_params = (const float*)d_in[3];   // [512, 1000]
    float* out = (float*)d_out;                         // [8192, 1000]

    cudaFuncSetAttribute(gemm1_kernel, cudaFuncAttributeMaxDynamicSharedMemorySize, STAGE_SMEM);
    cudaFuncSetAttribute(gemm2_kernel, cudaFuncAttributeMaxDynamicSharedMemorySize, STAGE_SMEM);

    prep_kernel<<<PREP_BLOCKS, 256>>>(xs, W, leaf_params);
    gemm1_kernel<<<dim3(4, 64), 256, STAGE_SMEM>>>(b);
    leaf_kernel<<<B_ROWS, 256>>>();
    gemm2_kernel<<<dim3(8, 64), 256, STAGE_SMEM>>>(out);
}

// round 17
// speedup vs baseline: 1.0667x; 1.0002x over previous
#include <cuda_runtime.h>
#include <cuda_fp16.h>
#include <cstdint>
#include <math.h>

// Problem constants
constexpr int B_ROWS = 8192;   // batch
constexpr int FDIM   = 4096;   // features
constexpr int NINT   = 511;    // internal nodes
constexpr int NPAD   = 512;    // padded internal dim
constexpr int NLEAF  = 512;
constexpr int KOUT   = 1000;
constexpr int NPAD2  = 1024;   // padded output-class dim

// Scratch (device globals; allocation is forbidden)
__device__ __half g_xh[(size_t)B_ROWS * FDIM];       // xs in fp16
__device__ __half g_wh[(size_t)NPAD * FDIM];         // W in fp16, row 511 zero
__device__ __half g_ps[(size_t)B_ROWS * NPAD];       // sigmoid(logits), fp16 (col 511 = 0.5, unused)
__device__ __half g_lp[(size_t)B_ROWS * NLEAF];      // leaf probabilities, fp16
__device__ __half g_distsT[(size_t)NPAD2 * NLEAF];   // softmax^T, rows [1000,1024) zero

// ---------------------------------------------------------------------------
// helpers
// ---------------------------------------------------------------------------
__device__ __forceinline__ uint32_t s2u(const void* p) {
    return (uint32_t)__cvta_generic_to_shared(p);
}

__device__ __forceinline__ void ldsm4(uint32_t* r, uint32_t addr) {
    asm volatile("ldmatrix.sync.aligned.m8n8.x4.shared.b16 {%0,%1,%2,%3}, [%4];"
        : "=r"(r[0]), "=r"(r[1]), "=r"(r[2]), "=r"(r[3]) : "r"(addr));
}

__device__ __forceinline__ void mma16(float* c, const uint32_t* a, uint32_t b0, uint32_t b1) {
    asm volatile(
        "mma.sync.aligned.m16n8k16.row.col.f32.f16.f16.f32 "
        "{%0,%1,%2,%3}, {%4,%5,%6,%7}, {%8,%9}, {%0,%1,%2,%3};\n"
        : "+f"(c[0]), "+f"(c[1]), "+f"(c[2]), "+f"(c[3])
        : "r"(a[0]), "r"(a[1]), "r"(a[2]), "r"(a[3]), "r"(b0), "r"(b1));
}

__device__ __forceinline__ void cpasync16(uint32_t dst, const void* src) {
    asm volatile("cp.async.cg.shared.global [%0], [%1], 16;" :: "r"(dst), "l"(src));
}

// mbarrier primitives
__device__ __forceinline__ void mbar_init(uint32_t a, uint32_t cnt) {
    asm volatile("mbarrier.init.shared.b64 [%0], %1;" :: "r"(a), "r"(cnt) : "memory");
}
__device__ __forceinline__ void mbar_arrive(uint32_t a) {
    asm volatile("mbarrier.arrive.shared.b64 _, [%0];" :: "r"(a) : "memory");
}
__device__ __forceinline__ void cp_arrive(uint32_t a) {
    asm volatile("cp.async.mbarrier.arrive.noinc.shared.b64 [%0];" :: "r"(a) : "memory");
}
__device__ __forceinline__ void mbar_wait(uint32_t a, uint32_t parity) {
    asm volatile(
        "{\n\t"
        ".reg .pred P;\n\t"
        "WAIT_%=:\n\t"
        "mbarrier.try_wait.parity.acquire.cta.shared::cta.b64 P, [%0], %1, 0x989680;\n\t"
        "@P bra.uni DONE_%=;\n\t"
        "bra.uni WAIT_%=;\n\t"
        "DONE_%=:\n\t"
        "}"
        :: "r"(a), "r"(parity) : "memory");
}

// 64B rows (32 halves), chunk 0..3 of 16B — XOR swizzle (validated R5/R8)
__device__ __forceinline__ uint32_t sw64(int row, int chunk) {
    return row * 64 + ((chunk ^ ((row >> 1) & 3)) << 4);
}

// pack 8 fp32 -> 8 fp16 in a uint4
__device__ __forceinline__ uint4 pack8(float4 a, float4 b) {
    uint4 r;
    __half2 h;
    h = __floats2half2_rn(a.x, a.y); r.x = *(uint32_t*)&h;
    h = __floats2half2_rn(a.z, a.w); r.y = *(uint32_t*)&h;
    h = __floats2half2_rn(b.x, b.y); r.z = *(uint32_t*)&h;
    h = __floats2half2_rn(b.z, b.w); r.w = *(uint32_t*)&h;
    return r;
}

// ---------------------------------------------------------------------------
// Merged prep kernel: conv_x | conv_w | softmax  (branch on blockIdx.x)
// ---------------------------------------------------------------------------
constexpr int PREP_CONVX  = (B_ROWS * FDIM) / (256 * 8);   // 16384
constexpr int PREP_CONVW  = (NPAD * FDIM) / (256 * 8);     // 1024
constexpr int PREP_BLOCKS = PREP_CONVX + PREP_CONVW + NLEAF;

__global__ void prep_kernel(const float* __restrict__ xs,
                            const float* __restrict__ W,
                            const float* __restrict__ lp)
{
    const int bx = blockIdx.x;
    const int tid = threadIdx.x;

    if (bx < PREP_CONVX) {
        const size_t i = ((size_t)bx * 256 + tid) * 8;
        const float4* s = (const float4*)(xs + i);
        *(uint4*)(g_xh + i) = pack8(s[0], s[1]);
        return;
    }
    if (bx < PREP_CONVX + PREP_CONVW) {
        const size_t i = ((size_t)(bx - PREP_CONVX) * 256 + tid) * 8;
        if (i < (size_t)NINT * FDIM) {
            const float4* s = (const float4*)(W + i);
            *(uint4*)(g_wh + i) = pack8(s[0], s[1]);
        } else {
            *(uint4*)(g_wh + i) = make_uint4(0, 0, 0, 0);
        }
        return;
    }

    // softmax for leaf row
    const int row = bx - PREP_CONVX - PREP_CONVW;
    const float* src = lp + (size_t)row * KOUT;
    __shared__ float red[8];
    __shared__ float se[KOUT];

    float m = -1e30f;
    for (int i = tid; i < KOUT; i += 256) { float v = src[i]; se[i] = v; m = fmaxf(m, v); }
    #pragma unroll
    for (int o = 16; o > 0; o >>= 1) m = fmaxf(m, __shfl_xor_sync(0xffffffffu, m, o));
    if ((tid & 31) == 0) red[tid >> 5] = m;
    __syncthreads();
    if (tid < 32) {
        float v = (tid < 8) ? red[tid] : -1e30f;
        #pragma unroll
        for (int o = 4; o > 0; o >>= 1) v = fmaxf(v, __shfl_xor_sync(0xffffffffu, v, o));
        if (tid == 0) red[0] = v;
    }
    __syncthreads();
    m = red[0];
    __syncthreads();

    float s = 0.f;
    for (int i = tid; i < KOUT; i += 256) { float e = __expf(se[i] - m); se[i] = e; s += e; }
    #pragma unroll
    for (int o = 16; o > 0; o >>= 1) s += __shfl_xor_sync(0xffffffffu, s, o);
    if ((tid & 31) == 0) red[tid >> 5] = s;
    __syncthreads();
    if (tid < 32) {
        float v = (tid < 8) ? red[tid] : 0.f;
        #pragma unroll
        for (int o = 4; o > 0; o >>= 1) v += __shfl_xor_sync(0xffffffffu, v, o);
        if (tid == 0) red[0] = v;
    }
    __syncthreads();
    const float inv = 1.f / red[0];
    for (int i = tid; i < KOUT; i += 256)
        g_distsT[(size_t)i * NLEAF + row] = __float2half_rn(se[i] * inv);
    for (int i = KOUT + tid; i < NPAD2; i += 256)
        g_distsT[(size_t)i * NLEAF + row] = __float2half_rn(0.f);
}

// ---------------------------------------------------------------------------
// Shared GEMM core (R16 base): CTA 128x128, 8 warps (32x64), BK=32,
// mbarrier ring 6 stages x 16KB, issue-ahead D=4, batched 12-LDSM schedule,
// statically scheduled ring.
// R17 change: within every step, (empty-wait + issue) is hoisted BEFORE
// compute — cp.asyncs for k+4 enter flight one full compute-phase earlier.
// Cross-iteration wait/arrive graph identical to the verified R16 schedule.
// ---------------------------------------------------------------------------
#define GEMM_CORE(Aptr, Astride, Bptr, Bstride, KT)                              \
    extern __shared__ __align__(16) char smem[];                                  \
    const uint32_t sb = s2u(smem);                                                \
    const uint32_t MBF = sb + 98304u;         /* full[6]  */                      \
    const uint32_t MBE = sb + 98304u + 48u;   /* empty[6] */                      \
    const int tid = threadIdx.x, warp = tid >> 5, lane = tid & 31;                \
    const int wm = warp & 3, wn = warp >> 2;                                      \
    const int tn = blockIdx.x, tm = blockIdx.y;                                   \
    if (tid == 0) {                                                               \
        _Pragma("unroll")                                                         \
        for (int s = 0; s < 6; s++) { mbar_init(MBF + s * 8, 256); mbar_init(MBE + s * 8, 256); } \
    }                                                                             \
    __syncthreads();                                                              \
    float c[2][8][4];                                                             \
    _Pragma("unroll")                                                             \
    for (int i = 0; i < 2; i++)                                                   \
        _Pragma("unroll")                                                         \
        for (int j = 0; j < 8; j++)                                               \
            _Pragma("unroll")                                                     \
            for (int k = 0; k < 4; k++) c[i][j][k] = 0.f;                         \
    uint32_t a_off[2], b_off[4];                                                  \
    {                                                                             \
        const int kc = lane >> 4;                                                 \
        _Pragma("unroll")                                                         \
        for (int mt = 0; mt < 2; mt++)                                            \
            a_off[mt] = sw64(wm * 32 + mt * 16 + (lane & 15), kc);                \
        _Pragma("unroll")                                                         \
        for (int nt = 0; nt < 4; nt++)                                            \
            b_off[nt] = 8192u + sw64(wn * 64 + nt * 16 + (lane & 15), kc);        \
    }                                                                             \
    const int lrow = tid >> 1, lch = (tid & 1) * 2;                               \
    const uint32_t st_a0 = sw64(lrow, lch), st_a1 = sw64(lrow, lch + 1);          \
    const __half* Ag = (Aptr) + (size_t)(tm * 128 + lrow) * (Astride) + (tid & 1) * 16; \
    const __half* Bg = (Bptr) + (size_t)(tn * 128 + lrow) * (Bstride) + (tid & 1) * 16; \
    auto issue = [&](int kn, int buf) {                                           \
        const uint32_t St = sb + buf * 16384;                                     \
        const __half* ag = Ag + kn * 32;                                          \
        const __half* bg = Bg + kn * 32;                                          \
        cpasync16(St + st_a0,        ag);                                         \
        cpasync16(St + st_a1,        ag + 8);                                     \
        cpasync16(St + 8192 + st_a0, bg);                                         \
        cpasync16(St + 8192 + st_a1, bg + 8);                                     \
        cp_arrive(MBF + buf * 8);                                                 \
    };                                                                            \
    auto compute = [&](int buf) {                                                 \
        const uint32_t St = sb + buf * 16384;                                     \
        uint32_t a[2][2][4], b[2][4][4];                                          \
        _Pragma("unroll")                                                         \
        for (int mt = 0; mt < 2; mt++) {                                          \
            ldsm4(a[0][mt], St + a_off[mt]);                                      \
            ldsm4(a[1][mt], St + (a_off[mt] ^ 0x20u));                            \
        }                                                                         \
        _Pragma("unroll")                                                         \
        for (int nt = 0; nt < 4; nt++) {                                          \
            ldsm4(b[0][nt], St + b_off[nt]);                                      \
            ldsm4(b[1][nt], St + (b_off[nt] ^ 0x20u));                            \
        }                                                                         \
        _Pragma("unroll")                                                         \
        for (int ks = 0; ks < 2; ks++)                                            \
            _Pragma("unroll")                                                     \
            for (int mt = 0; mt < 2; mt++)                                        \
                _Pragma("unroll")                                                 \
                for (int nt = 0; nt < 4; nt++) {                                  \
                    mma16(c[mt][nt * 2],     a[ks][mt], b[ks][nt][0], b[ks][nt][2]); \
                    mma16(c[mt][nt * 2 + 1], a[ks][mt], b[ks][nt][1], b[ks][nt][3]); \
                }                                                                 \
    };                                                                            \
    /* prologue: fill stages 0..3 */                                              \
    issue(0, 0); issue(1, 1); issue(2, 2); issue(3, 3);                           \
    /* peel kt=0..5: issue hoisted before compute (empty-waits from kt=2) */      \
    mbar_wait(MBF + 0,  0);                          issue(4, 4);                 \
        compute(0); mbar_arrive(MBE + 0);                                         \
    mbar_wait(MBF + 8,  0);                          issue(5, 5);                 \
        compute(1); mbar_arrive(MBE + 8);                                         \
    mbar_wait(MBF + 16, 0); mbar_wait(MBE + 0,  0);  issue(6, 0);                 \
        compute(2); mbar_arrive(MBE + 16);                                        \
    mbar_wait(MBF + 24, 0); mbar_wait(MBE + 8,  0);  issue(7, 1);                 \
        compute(3); mbar_arrive(MBE + 24);                                        \
    mbar_wait(MBF + 32, 0); mbar_wait(MBE + 16, 0);  issue(8, 2);                 \
        compute(4); mbar_arrive(MBE + 32);                                        \
    mbar_wait(MBF + 40, 0); mbar_wait(MBE + 24, 0);  issue(9, 3);                 \
        compute(5); mbar_arrive(MBE + 40);                                        \
    int fp = 1, rp = 0;                                                           \
    constexpr int TAILS = (((KT) - 10) / 6) * 6 + 6;                              \
    for (int kt0 = 6; kt0 < TAILS; kt0 += 6) {                                    \
        mbar_wait(MBF + 0,  fp); mbar_wait(MBE + 32, rp); issue(kt0 + 4, 4);      \
            compute(0); mbar_arrive(MBE + 0);                                     \
        mbar_wait(MBF + 8,  fp); mbar_wait(MBE + 40, rp); issue(kt0 + 5, 5);      \
            compute(1); mbar_arrive(MBE + 8);                                     \
        rp ^= 1;                                                                  \
        mbar_wait(MBF + 16, fp); mbar_wait(MBE + 0,  rp); issue(kt0 + 6, 0);      \
            compute(2); mbar_arrive(MBE + 16);                                    \
        mbar_wait(MBF + 24, fp); mbar_wait(MBE + 8,  rp); issue(kt0 + 7, 1);      \
            compute(3); mbar_arrive(MBE + 24);                                    \
        mbar_wait(MBF + 32, fp); mbar_wait(MBE + 16, rp); issue(kt0 + 8, 2);      \
            compute(4); mbar_arrive(MBE + 32);                                    \
        mbar_wait(MBF + 40, fp); mbar_wait(MBE + 24, rp); issue(kt0 + 9, 3);      \
            compute(5); mbar_arrive(MBE + 40);                                    \
        fp ^= 1;                                                                  \
    }                                                                             \
    /* tail: dynamic, continuing exact ring state (sc=0, rs=3, fp, rp) */         \
    {                                                                             \
        int sc = 0, rs = 3;                                                       \
        for (int kt = TAILS; kt < (KT); kt++) {                                   \
            mbar_wait(MBF + sc * 8, fp);                                          \
            const int kn = kt + 4;                                                \
            if (kn < (KT)) {                                                      \
                rs++; if (rs == 6) { rs = 0; rp ^= 1; }                           \
                mbar_wait(MBE + rs * 8, rp); issue(kn, rs);                       \
            }                                                                     \
            compute(sc);                                                          \
            mbar_arrive(MBE + sc * 8);                                            \
            sc++; if (sc == 6) { sc = 0; fp ^= 1; }                               \
        }                                                                         \
    }

constexpr int STAGE_SMEM = 6 * 16384 + 128;   // 96KB stages + mbarriers

// ---------------------------------------------------------------------------
// GEMM1: ps = sigmoid(xh @ wh^T + b)   grid (4, 64), 256 threads, fp16 out
// ---------------------------------------------------------------------------
__global__ __launch_bounds__(256, 2)
void gemm1_kernel(const float* __restrict__ bias)
{
    GEMM_CORE(g_xh, FDIM, g_wh, FDIM, FDIM / 32)

    const int g = lane >> 2, tg = lane & 3;
    #pragma unroll
    for (int mt = 0; mt < 2; mt++) {
        #pragma unroll
        for (int j = 0; j < 8; j++) {
            const int col = tn * 128 + wn * 64 + j * 8 + 2 * tg;
            const float bb0 = (col     < NINT) ? __ldg(bias + col)     : 0.f;
            const float bb1 = (col + 1 < NINT) ? __ldg(bias + col + 1) : 0.f;
            const int row0 = tm * 128 + wm * 32 + mt * 16 + g;
            float v0 = c[mt][j][0] + bb0;
            float v1 = c[mt][j][1] + bb1;
            float v2 = c[mt][j][2] + bb0;
            float v3 = c[mt][j][3] + bb1;
            __half2 p0 = __floats2half2_rn(1.f / (1.f + __expf(-v0)), 1.f / (1.f + __expf(-v1)));
            __half2 p1 = __floats2half2_rn(1.f / (1.f + __expf(-v2)), 1.f / (1.f + __expf(-v3)));
            *(__half2*)&g_ps[(size_t)row0       * NPAD + col] = p0;
            *(__half2*)&g_ps[(size_t)(row0 + 8) * NPAD + col] = p1;
        }
    }
}

// ---------------------------------------------------------------------------
// GEMM2: out = leaf_prob[8192,512] @ distsT^T[512, 1024pad]   grid (8, 64)
// ---------------------------------------------------------------------------
__global__ __launch_bounds__(256, 2)
void gemm2_kernel(float* __restrict__ out)
{
    GEMM_CORE(g_lp, NLEAF, g_distsT, NLEAF, NLEAF / 32)

    const int g = lane >> 2, tg = lane & 3;
    #pragma unroll
    for (int mt = 0; mt < 2; mt++) {
        #pragma unroll
        for (int j = 0; j < 8; j++) {
            const int col = tn * 128 + wn * 64 + j * 8 + 2 * tg;
            if (col < KOUT) {   // col even, KOUT even -> pair in-bounds
                const int row0 = tm * 128 + wm * 32 + mt * 16 + g;
                *(float2*)&out[(size_t)row0       * KOUT + col] =
                    make_float2(c[mt][j][0], c[mt][j][1]);
                *(float2*)&out[(size_t)(row0 + 8) * KOUT + col] =
                    make_float2(c[mt][j][2], c[mt][j][3]);
            }
        }
    }
}

// ---------------------------------------------------------------------------
// Leaf probabilities: one block per row, 256 threads x 2 leaves, fp16 in/out
// ---------------------------------------------------------------------------
__global__ __launch_bounds__(256)
void leaf_kernel()
{
    __shared__ float sp[NPAD];
    const int row = blockIdx.x;
    const int tid = threadIdx.x;
    {
        const __half2 h = *(const __half2*)&g_ps[(size_t)row * NPAD + 2 * tid];
        const float2 f = __half22float2(h);
        sp[2 * tid]     = f.x;
        sp[2 * tid + 1] = f.y;
    }
    __syncthreads();
    #pragma unroll
    for (int r = 0; r < 2; r++) {
        const int j = tid + r * 256;
        float prod = 1.f;
        int node = 0;
        #pragma unroll
        for (int t = 0; t < 9; t++) {
            const int bit = (j >> (8 - t)) & 1;
            const float p = sp[node];
            prod *= bit ? p : (1.f - p);
            node = 2 * node + 1 + bit;
        }
        g_lp[(size_t)row * NLEAF + j] = __float2half_rn(prod);
    }
}

// ---------------------------------------------------------------------------
// Launch
// ---------------------------------------------------------------------------
extern "C" void kernel_launch(void* const* d_in, const int* in_sizes, int n_in,
                              void* d_out, int out_size)
{
    const float* xs          = (const float*)d_in[0];   // [8192, 4096]
    const float* W           = (const float*)d_in[1];   // [511, 4096]
    const float* b           = (const float*)d_in[2];   // [511]
    const float* leaf_params = (const float*)d_in[3];   // [512, 1000]
    float* out = (float*)d_out;                         // [8192, 1000]

    cudaFuncSetAttribute(gemm1_kernel, cudaFuncAttributeMaxDynamicSharedMemorySize, STAGE_SMEM);
    cudaFuncSetAttribute(gemm2_kernel, cudaFuncAttributeMaxDynamicSharedMemorySize, STAGE_SMEM);

    prep_kernel<<<PREP_BLOCKS, 256>>>(xs, W, leaf_params);
    gemm1_kernel<<<dim3(4, 64), 256, STAGE_SMEM>>>(b);
    leaf_kernel<<<B_ROWS, 256>>>();
    gemm2_kernel<<<dim3(8, 64), 256, STAGE_SMEM>>>(out);
}